// round 17
// baseline (speedup 1.0000x reference)
#include <cuda_runtime.h>
#include <stdint.h>

#define BB 16
#define NN 4096
#define DD 32
#define CC 64
#define KK 16
#define KA 32           // approx survivors per query (register-resident, sorted)
#define CAPA 64         // phase-A per-lane stack depth
#define E2 0.5f         // certified margin >= 2 * tf32 dot error bound

typedef unsigned long long u64;
typedef unsigned int u32;

// ---------------- phase-A dynamic smem layout ----------------
#define CPAD 36                          // cand tile row stride (floats)
#define MPAD 34                          // m tile row stride (floats, even)
#define SZ_C     (128 * CPAD * 4)        // 18432
#define SZ_RC    (128 * 4)               // 512
#define SZ_M_W   (32 * MPAD * 4)         // 4352 per warp
#define SZ_STK_W (CAPA * 32 * 8)         // 16384 per warp
#define OFF_C    0
#define OFF_RC   SZ_C
#define OFF_M    (SZ_C + SZ_RC)
#define OFF_STK  (OFF_M + 4 * SZ_M_W)
#define SMEM_A_TOTAL (OFF_STK + 4 * SZ_STK_W)   // 101888

__device__ float g_norms[BB * NN];
__device__ u64   g_part[(size_t)BB * NN * KA];

__device__ __forceinline__ u32 to_tf32(float x) {
    u32 r; asm("cvt.rna.tf32.f32 %0, %1;" : "=r"(r) : "f"(x));
    return r;
}
__device__ __forceinline__ void mma_tf32(float& d0, float& d1, float& d2, float& d3,
                                         u32 a0, u32 a1, u32 a2, u32 a3,
                                         u32 b0, u32 b1) {
    asm volatile(
        "mma.sync.aligned.m16n8k8.row.col.f32.tf32.tf32.f32 "
        "{%0,%1,%2,%3}, {%4,%5,%6,%7}, {%8,%9}, {%0,%1,%2,%3};"
        : "+f"(d0), "+f"(d1), "+f"(d2), "+f"(d3)
        : "r"(a0), "r"(a1), "r"(a2), "r"(a3), "r"(b0), "r"(b1));
}

__device__ __forceinline__ float tree32f(float t[32]) {
    #pragma unroll
    for (int off = 16; off >= 1; off >>= 1)
        #pragma unroll
        for (int i = 0; i < off; ++i)
            t[i] = __fadd_rn(t[i], t[i + off]);
    return t[0];
}
template <int K>
__device__ __forceinline__ void insK(u64 (&k)[K], u64 nk) {
    #pragma unroll
    for (int s = K - 1; s >= 1; --s) {
        u64 mn = (nk < k[s]) ? nk : k[s];
        k[s] = (k[s-1] > mn) ? k[s-1] : mn;
    }
    k[0] = (nk < k[0]) ? nk : k[0];
}
__device__ __forceinline__ float keyval(u64 wk) {
    u32 hi = (u32)(wk >> 32) & 0x7fffffffu;
    hi = hi < 0x7f800000u ? hi : 0x7f800000u;
    return __uint_as_float(hi);
}

__global__ void norms_kernel(const float* __restrict__ points) {
    int idx = blockIdx.x * blockDim.x + threadIdx.x;
    if (idx >= BB * NN) return;
    const float4* cp = (const float4*)(points + (size_t)idx * DD);
    float x[32];
    #pragma unroll
    for (int j4 = 0; j4 < 8; ++j4) {
        float4 v = __ldg(cp + j4);
        x[j4*4+0] = __fmul_rn(v.x, v.x); x[j4*4+1] = __fmul_rn(v.y, v.y);
        x[j4*4+2] = __fmul_rn(v.z, v.z); x[j4*4+3] = __fmul_rn(v.w, v.w);
    }
    g_norms[idx] = tree32f(x);
}

// ================= Phase A: tf32 mma.sync filter =================
__global__ __launch_bounds__(128, 2)
void filter_kernel(const float* __restrict__ points)
{
    extern __shared__ char smem[];
    float* s_c  = (float*)(smem + OFF_C);     // [128][CPAD]
    float* s_rc = (float*)(smem + OFF_RC);
    const int lane = threadIdx.x & 31;
    const int warp = threadIdx.x >> 5;
    const int b  = blockIdx.x >> 5;
    const int q0 = (blockIdx.x & 31) * 128;
    const int nq = q0 + warp * 32 + lane;
    const unsigned FULL = 0xffffffffu;

    float* s_mw = (float*)(smem + OFF_M + warp * SZ_M_W);    // [32][MPAD]
    u64*   stk  = (u64*)(smem + OFF_STK + warp * SZ_STK_W);

    const float* pb = points + (size_t)b * NN * DD;

    // ---- stage this CTA's 128 queries into s_c, build A fragments ----
    {
        const float4* src = (const float4*)(pb + (size_t)q0 * DD);
        #pragma unroll
        for (int it = 0; it < 8; ++it) {
            int v = threadIdx.x + it * 128;
            int c = v >> 3, j4 = v & 7;
            *(float4*)&s_c[c * CPAD + j4 * 4] = src[v];
        }
    }
    __syncthreads();

    u32 afr[2][4][4];   // [mtile][kstep][frag]
    {
        const int gid = lane >> 2, tid4 = lane & 3;
        #pragma unroll
        for (int t = 0; t < 2; ++t)
            #pragma unroll
            for (int ks = 0; ks < 4; ++ks) {
                const float* qr0 = &s_c[(warp * 32 + t * 16 + gid) * CPAD + ks * 8];
                const float* qr8 = qr0 + 8 * CPAD;
                afr[t][ks][0] = to_tf32(qr0[tid4]);
                afr[t][ks][1] = to_tf32(qr8[tid4]);
                afr[t][ks][2] = to_tf32(qr0[tid4 + 4]);
                afr[t][ks][3] = to_tf32(qr8[tid4 + 4]);
            }
    }
    __syncthreads();

    const float rqb = __ldg(&g_norms[b * NN + nq]) + 4.0f;   // bias keeps D~ > 0
    u64 k[KA];
    #pragma unroll
    for (int i = 0; i < KA; ++i) k[i] = ~0ull;
    float wq = __int_as_float(0x7f800000);
    int cnt = 0;

    for (int tile = 0; tile < NN / 128; ++tile) {
        __syncthreads();
        {   // candidate tile 128x32 into s_c + norms
            const float4* src = (const float4*)(pb + (size_t)tile * 128 * DD);
            #pragma unroll
            for (int it = 0; it < 8; ++it) {
                int v = threadIdx.x + it * 128;
                int c = v >> 3, j4 = v & 7;
                *(float4*)&s_c[c * CPAD + j4 * 4] = src[v];
            }
            if (threadIdx.x < 32)
                *(float4*)&s_rc[threadIdx.x * 4] =
                    *(const float4*)&g_norms[b * NN + tile * 128 + threadIdx.x * 4];
        }
        __syncthreads();

        const int gid = lane >> 2, tid4 = lane & 3;
        #pragma unroll 1
        for (int g = 0; g < 4; ++g) {           // 32-candidate groups
            const int cg = g * 32;
            float acc[2][4][4];
            #pragma unroll
            for (int t = 0; t < 2; ++t)
                #pragma unroll
                for (int nt = 0; nt < 4; ++nt)
                    #pragma unroll
                    for (int e = 0; e < 4; ++e) acc[t][nt][e] = 0.f;

            #pragma unroll
            for (int ks = 0; ks < 4; ++ks) {
                u32 bf[4][2];
                #pragma unroll
                for (int nt = 0; nt < 4; ++nt) {
                    const float* cr = &s_c[(cg + nt * 8 + gid) * CPAD + ks * 8];
                    bf[nt][0] = to_tf32(cr[tid4]);
                    bf[nt][1] = to_tf32(cr[tid4 + 4]);
                }
                #pragma unroll
                for (int t = 0; t < 2; ++t)
                    #pragma unroll
                    for (int nt = 0; nt < 4; ++nt)
                        mma_tf32(acc[t][nt][0], acc[t][nt][1],
                                 acc[t][nt][2], acc[t][nt][3],
                                 afr[t][ks][0], afr[t][ks][1],
                                 afr[t][ks][2], afr[t][ks][3],
                                 bf[nt][0], bf[nt][1]);
            }

            // scatter m-tile into s_mw[q][c] (float2 stores)
            #pragma unroll
            for (int t = 0; t < 2; ++t)
                #pragma unroll
                for (int nt = 0; nt < 4; ++nt) {
                    int col = nt * 8 + 2 * tid4;
                    *(float2*)&s_mw[(t * 16 + gid) * MPAD + col] =
                        make_float2(acc[t][nt][0], acc[t][nt][1]);
                    *(float2*)&s_mw[(t * 16 + gid + 8) * MPAD + col] =
                        make_float2(acc[t][nt][2], acc[t][nt][3]);
                }
            __syncwarp();

            // per-lane selection on 32 approx distances (lane = query row)
            float da[32];
            #pragma unroll
            for (int i2 = 0; i2 < 16; ++i2) {
                float2 mv = *(const float2*)&s_mw[lane * MPAD + i2 * 2];
                da[i2*2]   = __fadd_rn(__fmaf_rn(-2.f, mv.x, rqb), s_rc[cg + i2*2]);
                da[i2*2+1] = __fadd_rn(__fmaf_rn(-2.f, mv.y, rqb), s_rc[cg + i2*2+1]);
            }
            u32 pm = 0;
            #pragma unroll
            for (int i = 0; i < 32; ++i) pm |= (da[i] <= wq) ? (1u << i) : 0u;
            if (__any_sync(FULL, pm)) {
                const int gi0 = tile * 128 + cg;
                #pragma unroll
                for (int i = 0; i < 32; ++i) {
                    if (pm & (1u << i)) {
                        int pos = cnt + __popc(pm & ((1u << i) - 1u));
                        u32 h = __float_as_uint(da[i]) | 0x80000000u;
                        stk[pos * 32 + lane] = ((u64)h << 32) | (u32)(gi0 + i);
                    }
                }
                cnt += __popc(pm);
                if (__any_sync(FULL, cnt > CAPA - 32)) {
                    unsigned mx = __reduce_max_sync(FULL, (unsigned)cnt);
                    for (unsigned e = 0; e < mx; ++e) {
                        u64 v = (e < (unsigned)cnt) ? stk[e * 32 + lane] : ~0ull;
                        insK<KA>(k, v);
                    }
                    cnt = 0;
                    wq = keyval(k[KA - 1]);
                }
            }
            __syncwarp();   // s_mw reuse by next group
        }
    }

    // final drain
    {
        unsigned mx = __reduce_max_sync(FULL, (unsigned)cnt);
        for (unsigned e = 0; e < mx; ++e) {
            u64 v = (e < (unsigned)cnt) ? stk[e * 32 + lane] : ~0ull;
            insK<KA>(k, v);
        }
    }
    // write sorted approx top-32 keys
    u64* dst = &g_part[((size_t)(b * NN + nq)) * KA];
    #pragma unroll
    for (int i = 0; i < KA; ++i) dst[i] = k[i];
}

// ================= Phase B: certified exact rescore + output =================
__global__ __launch_bounds__(128, 4)
void rescore_kernel(const float* __restrict__ points,
                    const float* __restrict__ features,
                    float* __restrict__ out)
{
    __shared__ int s_idx[128][KK];
    const int lane = threadIdx.x & 31;
    const int warp = threadIdx.x >> 5;
    const int b  = blockIdx.x >> 5;
    const int q0 = (blockIdx.x & 31) * 128;
    const int n  = q0 + warp * 32 + lane;

    const float* pb = points   + (size_t)b * NN * DD;
    const float* fb = features + (size_t)b * NN * CC;

    float qs[32];
    {
        const float4* qp = (const float4*)(pb + (size_t)n * DD);
        #pragma unroll
        for (int j4 = 0; j4 < 8; ++j4) {
            float4 v = __ldg(qp + j4);
            qs[j4*4+0] = v.x; qs[j4*4+1] = v.y; qs[j4*4+2] = v.z; qs[j4*4+3] = v.w;
        }
    }
    const float rq = __ldg(&g_norms[b * NN + n]);

    u64 k[KK];
    #pragma unroll
    for (int i = 0; i < KK; ++i) k[i] = ~0ull;

    const u64* keys = &g_part[((size_t)(b * NN + n)) * KA];

    // exact distance, bitwise-identical to the reference composition
    auto exact_key = [&](int ci) -> u64 {
        const float4* cp = (const float4*)(pb + (size_t)ci * DD);
        float m = 0.f;
        #pragma unroll
        for (int j4 = 0; j4 < 8; ++j4) {
            float4 v = __ldg(cp + j4);
            m = __fmaf_rn(qs[j4*4+0], v.x, m);
            m = __fmaf_rn(qs[j4*4+1], v.y, m);
            m = __fmaf_rn(qs[j4*4+2], v.z, m);
            m = __fmaf_rn(qs[j4*4+3], v.w, m);
        }
        float d = __fadd_rn(__fmaf_rn(-2.f, m, rq), __ldg(&g_norms[b * NN + ci]));
        u32 h = __float_as_uint(d) | 0x80000000u;
        return ((u64)h << 32) | (u32)ci;
    };

    // certificate: 32nd approx strictly beyond 17th approx + margin
    const float t17 = keyval(__ldg(&keys[16]));
    const float t32 = keyval(__ldg(&keys[31]));
    if (t32 > t17 + E2) {
        #pragma unroll
        for (int i = 0; i < KA; ++i) {
            u32 ci = (u32)__ldg(&keys[i]);
            if (ci >= (u32)NN || (int)ci == n) continue;
            insK<KK>(k, exact_key((int)ci));
        }
    } else {
        // fallback: full exact scan (slow-correct; ~never executes)
        for (int ci = 0; ci < NN; ++ci)
            if (ci != n) insK<KK>(k, exact_key(ci));
    }

    #pragma unroll
    for (int kk = 0; kk < KK; ++kk) s_idx[warp * 32 + lane][kk] = (int)(u32)k[kk];
    __syncwarp();

    // gather + write (proven epilogue): 2 contiguous channels per lane
    const int l2 = lane * 2;
    for (int qq = 0; qq < 32; ++qq) {
        int nn2 = q0 + warp * 32 + qq;
        float2 c = *(const float2*)(fb + (size_t)nn2 * CC + l2);
        float* ob = out + (size_t)(b * NN + nn2) * KK * (2 * CC);
        #pragma unroll
        for (int kk = 0; kk < KK; ++kk) {
            int nbv = s_idx[warp * 32 + qq][kk];
            float2 g = *(const float2*)(fb + (size_t)nbv * CC + l2);
            float* orow = ob + kk * (2 * CC);
            __stcs((float2*)(orow + l2), g);
            __stcs((float2*)(orow + 64 + l2), make_float2(g.x - c.x, g.y - c.y));
        }
    }
}

extern "C" void kernel_launch(void* const* d_in, const int* in_sizes, int n_in,
                              void* d_out, int out_size) {
    const float* points   = (const float*)d_in[0];
    const float* features = (const float*)d_in[1];
    float* out = (float*)d_out;
    (void)in_sizes; (void)n_in; (void)out_size;
    cudaFuncSetAttribute(filter_kernel,
                         cudaFuncAttributeMaxDynamicSharedMemorySize, SMEM_A_TOTAL);
    norms_kernel<<<(BB * NN + 255) / 256, 256>>>(points);
    filter_kernel<<<BB * 32, 128, SMEM_A_TOTAL>>>(points);
    rescore_kernel<<<BB * 32, 128>>>(points, features, out);
}